// round 16
// baseline (speedup 1.0000x reference)
#include <cuda_runtime.h>
#include <cuda_fp16.h>
#include <math.h>

#define BATCH 4
#define NPTS  40960
#define KNN   16
#define P_TOTAL (BATCH * NPTS)   // 163840
#define PHALF  (P_TOTAL / 2)

#define FS_H2  36    // fs/elg tile row stride in half2 units (4 mod 32)
#define WH64   68    // fp16 B-tile stride, 64 cols, uint2 units
#define WH32   36    // fp16 B-tile stride, 32 cols, uint2 units
#define P2F64  68    // float2 B-tile stride, 64 cols (4 mod 16)
#define P2F128 132   // float2 B-tile stride, 128 cols (4 mod 16)
#define RP2    12    // relpos tile stride in half2 units
#define OA_PAD 100   // kern_out A tile stride (4 mod 32)

// Scratch (device globals) -- gathered tensors stored pre-packed fp16
__device__ __half2 g_f_pc_h [P_TOTAL * 16];                  // 10.5 MB
__device__ __half2 g_f_agg_h[P_TOTAL * 16];                  // 10.5 MB
__device__ float   g_agg2 [(size_t)P_TOTAL * 64];            // 42 MB
__device__ __half2 g_fx2  [(size_t)P_TOTAL * KNN * 16];      // 168 MB

__device__ __forceinline__ float to_tf32(float x) {
    float r;
    asm("cvt.rna.tf32.f32 %0, %1;" : "=f"(r) : "f"(x));
    return r;
}
__device__ __forceinline__ unsigned f2_to_u(float a, float b) {
    __half2 h = __floats2half2_rn(a, b);
    return *(unsigned*)&h;
}

__device__ __forceinline__ void mma_tf32(float* c,
                                         unsigned a0, unsigned a1, unsigned a2, unsigned a3,
                                         unsigned b0, unsigned b1) {
    asm("mma.sync.aligned.m16n8k8.row.col.f32.tf32.tf32.f32 "
        "{%0,%1,%2,%3}, {%4,%5,%6,%7}, {%8,%9}, {%0,%1,%2,%3};"
        : "+f"(c[0]), "+f"(c[1]), "+f"(c[2]), "+f"(c[3])
        : "r"(a0), "r"(a1), "r"(a2), "r"(a3), "r"(b0), "r"(b1));
}
__device__ __forceinline__ void mma_f16(float* c,
                                        unsigned a0, unsigned a1, unsigned a2, unsigned a3,
                                        unsigned b0, unsigned b1) {
    asm("mma.sync.aligned.m16n8k16.row.col.f32.f16.f16.f32 "
        "{%0,%1,%2,%3}, {%4,%5,%6,%7}, {%8,%9}, {%0,%1,%2,%3};"
        : "+f"(c[0]), "+f"(c[1]), "+f"(c[2]), "+f"(c[3])
        : "r"(a0), "r"(a1), "r"(a2), "r"(a3), "r"(b0), "r"(b1));
}

// dual-point logits -> exp(logit-8) stored as fp16 weight tiles (elg).
__device__ __forceinline__ void logits_exp_x2(const unsigned* __restrict__ fsw0,
                                              const unsigned* __restrict__ fsw1,
                                              __half2* __restrict__ elg0,
                                              __half2* __restrict__ elg1,
                                              const uint2* __restrict__ wfc, int lane)
{
    const int gid = lane >> 2;
    const int tig = lane & 3;
    float ac0[8][4], ac1[8][4];
    #pragma unroll
    for (int n = 0; n < 8; n++)
        #pragma unroll
        for (int j = 0; j < 4; j++) { ac0[n][j] = 0.f; ac1[n][j] = 0.f; }
    #pragma unroll
    for (int q = 0; q < 4; q++) {
        unsigned a00 = fsw0[gid * FS_H2 + q * 8 + tig];
        unsigned a01 = fsw0[(gid + 8) * FS_H2 + q * 8 + tig];
        unsigned a02 = fsw0[gid * FS_H2 + q * 8 + tig + 4];
        unsigned a03 = fsw0[(gid + 8) * FS_H2 + q * 8 + tig + 4];
        unsigned a10 = fsw1[gid * FS_H2 + q * 8 + tig];
        unsigned a11 = fsw1[(gid + 8) * FS_H2 + q * 8 + tig];
        unsigned a12 = fsw1[gid * FS_H2 + q * 8 + tig + 4];
        unsigned a13 = fsw1[(gid + 8) * FS_H2 + q * 8 + tig + 4];
        const uint2* br = wfc + (q * 4 + tig) * WH64 + gid;
        #pragma unroll
        for (int n = 0; n < 8; n++) {
            uint2 b = br[8 * n];
            mma_f16(ac0[n], a00, a01, a02, a03, b.x, b.y);
            mma_f16(ac1[n], a10, a11, a12, a13, b.x, b.y);
        }
    }
    #pragma unroll
    for (int n = 0; n < 8; n++) {
        elg0[gid * FS_H2 + n * 4 + tig] =
            __floats2half2_rn(__expf(ac0[n][0] - 8.f), __expf(ac0[n][1] - 8.f));
        elg0[(gid + 8) * FS_H2 + n * 4 + tig] =
            __floats2half2_rn(__expf(ac0[n][2] - 8.f), __expf(ac0[n][3] - 8.f));
        elg1[gid * FS_H2 + n * 4 + tig] =
            __floats2half2_rn(__expf(ac1[n][0] - 8.f), __expf(ac1[n][1] - 8.f));
        elg1[(gid + 8) * FS_H2 + n * 4 + tig] =
            __floats2half2_rn(__expf(ac1[n][2] - 8.f), __expf(ac1[n][3] - 8.f));
    }
}

// Pool for channel pair (2*lane, 2*lane+1): conflict-free half2 loads.
__device__ __forceinline__ float2 att_pool_e2(const __half2* __restrict__ elg,
                                              const __half2* __restrict__ fs_h, int lane)
{
    float sx0 = 0.f, ax0 = 0.f, sx1 = 0.f, ax1 = 0.f;
    float sy0 = 0.f, ay0 = 0.f, sy1 = 0.f, ay1 = 0.f;
    #pragma unroll
    for (int k = 0; k < KNN; k += 2) {
        float2 e0 = __half22float2(elg[k * FS_H2 + lane]);
        float2 v0 = __half22float2(fs_h[k * FS_H2 + lane]);
        float2 e1 = __half22float2(elg[(k + 1) * FS_H2 + lane]);
        float2 v1 = __half22float2(fs_h[(k + 1) * FS_H2 + lane]);
        sx0 += e0.x; ax0 += e0.x * v0.x;
        sy0 += e0.y; ay0 += e0.y * v0.y;
        sx1 += e1.x; ax1 += e1.x * v1.x;
        sy1 += e1.y; ay1 += e1.y * v1.y;
    }
    return make_float2(__fdividef(ax0 + ax1, sx0 + sx1),
                       __fdividef(ay0 + ay1, sy0 + sy1));
}

// ---------------------------------------------------------------------------
// Kernel 1: f_pc = ReLU((feature @ w_mlp1) * s + b) -> fp16 packed
// ---------------------------------------------------------------------------
__global__ __launch_bounds__(256) void kern_mlp1(
    const float* __restrict__ feature,
    const float* __restrict__ w, const float* __restrict__ s, const float* __restrict__ b)
{
    __shared__ float xs[8][32];

    const int lane = threadIdx.x & 31;
    const int warp = threadIdx.x >> 5;

    float wcol[32];
    #pragma unroll
    for (int j = 0; j < 32; j++) wcol[j] = w[j * 32 + lane];
    const float sv = s[lane];
    const float bv = b[lane];

    unsigned* dst = (unsigned*)g_f_pc_h;

    const int nwarps = (gridDim.x * blockDim.x) >> 5;
    int gw = (blockIdx.x * blockDim.x + threadIdx.x) >> 5;

    for (int p = gw; p < P_TOTAL; p += nwarps) {
        xs[warp][lane] = feature[(size_t)p * 32 + lane];
        __syncwarp();
        float acc = 0.f;
        #pragma unroll
        for (int j4 = 0; j4 < 32; j4 += 4) {
            float4 f = *(const float4*)(&xs[warp][j4]);
            acc += f.x * wcol[j4] + f.y * wcol[j4 + 1]
                 + f.z * wcol[j4 + 2] + f.w * wcol[j4 + 3];
        }
        float o = fmaxf(acc * sv + bv, 0.f);
        float o1 = __shfl_xor_sync(0xffffffffu, o, 1);
        if (!(lane & 1))
            dst[(size_t)p * 16 + (lane >> 1)] = f2_to_u(o, o1);
        __syncwarp();
    }
}

// ---------------------------------------------------------------------------
// Kernel 2: TWO points per warp. Prefetched idx; rel_pos + lfa1(f16) +
//           direct fp16 gather + logits->exp + pool + f_agg ; lfa2 -> g_fx2.
// ---------------------------------------------------------------------------
#define K2_WARP_FLOATS 2432
#define K2_BASE_FLOATS 5216
#define K2_WARPS 20
#define K2_SMEM_BYTES ((K2_BASE_FLOATS + K2_WARPS * K2_WARP_FLOATS) * 4)

__global__ __launch_bounds__(640) void kern_att1(
    const float* __restrict__ xyz, const int* __restrict__ neigh,
    const float* __restrict__ wlfa1, const float* __restrict__ slfa1, const float* __restrict__ blfa1,
    const float* __restrict__ wfc1,
    const float* __restrict__ wam1, const float* __restrict__ sam1, const float* __restrict__ bam1,
    const float* __restrict__ wlfa2, const float* __restrict__ slfa2, const float* __restrict__ blfa2)
{
    extern __shared__ float sm[];
    uint2*  s_wfcp = (uint2*)sm;              // [16][68] uint2 = 2176 floats
    float2* s_wamp = (float2*)(sm + 2176);    // [32][32] float2 = 2048 floats
    uint2*  s_wl1p = (uint2*)(sm + 4224);     // [4][36] uint2 = 288 floats
    uint2*  s_wl2p = (uint2*)(sm + 4512);     // [8][36] uint2 = 576 floats
    float*  s_vec  = sm + 5088;               // 128: blfa1, blfa2, bam1
    float*  s_wrp  = sm + K2_BASE_FLOATS;

    for (int i = threadIdx.x; i < 1024; i += blockDim.x) {
        int r = i >> 6, c = i & 63;
        int q = r >> 2, t = r & 3;
        int k0 = 16 * q + 2 * t;
        s_wfcp[r * WH64 + c] = make_uint2(
            f2_to_u(wfc1[k0 * 64 + c], wfc1[(k0 + 1) * 64 + c]),
            f2_to_u(wfc1[(k0 + 8) * 64 + c], wfc1[(k0 + 9) * 64 + c]));
    }
    for (int i = threadIdx.x; i < 1024; i += blockDim.x) {
        int r = i >> 5, c = i & 31;
        s_wamp[r * 32 + c] = make_float2(wam1[(2 * r) * 32 + c] * sam1[c],
                                         wam1[(2 * r + 1) * 32 + c] * sam1[c]);
    }
    for (int i = threadIdx.x; i < 128; i += blockDim.x) {
        int t = i >> 5, c = i & 31;
        int k0 = 2 * t, k1 = 2 * t + 8;
        float w00 = wlfa1[k0 * 32 + c] * slfa1[c];
        float w01 = wlfa1[(k0 + 1) * 32 + c] * slfa1[c];
        float w10 = (k1 < 10) ? wlfa1[k1 * 32 + c] * slfa1[c] : 0.f;
        float w11 = (k1 + 1 < 10) ? wlfa1[(k1 + 1) * 32 + c] * slfa1[c] : 0.f;
        s_wl1p[t * WH32 + c] = make_uint2(f2_to_u(w00, w01), f2_to_u(w10, w11));
    }
    for (int i = threadIdx.x; i < 256; i += blockDim.x) {
        int r = i >> 5, c = i & 31;
        int q = r >> 2, t = r & 3;
        int k0 = 16 * q + 2 * t;
        s_wl2p[r * WH32 + c] = make_uint2(
            f2_to_u(wlfa2[k0 * 32 + c] * slfa2[c], wlfa2[(k0 + 1) * 32 + c] * slfa2[c]),
            f2_to_u(wlfa2[(k0 + 8) * 32 + c] * slfa2[c], wlfa2[(k0 + 9) * 32 + c] * slfa2[c]));
    }
    if (threadIdx.x < 32) {
        int l = threadIdx.x;
        s_vec[l]      = blfa1[l];
        s_vec[32 + l] = blfa2[l];
        s_vec[64 + l] = bam1[l];
    }
    __syncthreads();

    const int lane = threadIdx.x & 31;
    const int warp = threadIdx.x >> 5;
    const int gid = lane >> 2, tig = lane & 3;
    const int kk = lane >> 4, jj = lane & 15;
    float* wbase = s_wrp + warp * K2_WARP_FLOATS;
    __half2*  fs0_h = (__half2*)wbase;            // [16][36] half2
    __half2*  fs1_h = (__half2*)(wbase + 576);
    unsigned* fsw0  = (unsigned*)fs0_h;
    unsigned* fsw1  = (unsigned*)fs1_h;
    __half2*  elg0  = (__half2*)(wbase + 1152);   // [16][36] half2 (weights)
    __half2*  elg1  = (__half2*)(wbase + 1728);
    __half2*  rp0   = elg0;                       // relpos aliases elg (dead)
    __half2*  rp1   = elg1;
    unsigned* rp0w  = (unsigned*)rp0;
    unsigned* rp1w  = (unsigned*)rp1;
    float* agg_s = wbase + 2304;                  // [128]

    const unsigned* pc = (const unsigned*)g_f_pc_h;
    unsigned* fah = (unsigned*)g_f_agg_h;

    const int nwarps = (gridDim.x * blockDim.x) >> 5;
    int gw = (blockIdx.x * blockDim.x + threadIdx.x) >> 5;

    // prefetch first iteration's neighbor row
    int idx = (gw < PHALF) ? neigh[(size_t)(2 * gw) * KNN + lane] : 0;

    for (int pp = gw; pp < PHALF; pp += nwarps) {
        const int p0 = 2 * pp, p1 = p0 + 1;
        const int b = p0 / NPTS;
        const size_t bbase = (size_t)b * NPTS;

        // direct fp16 gather: 2 rows per pass, lane (kk,jj)
        #pragma unroll
        for (int k = 0; k < KNN; k += 2) {
            int nb = __shfl_sync(0xffffffffu, idx, k + kk);
            fsw0[(k + kk) * FS_H2 + jj] = pc[(bbase + (size_t)nb) * 16 + jj];
        }
        #pragma unroll
        for (int k = 0; k < KNN; k += 2) {
            int nb = __shfl_sync(0xffffffffu, idx, 16 + k + kk);
            fsw1[(k + kk) * FS_H2 + jj] = pc[(bbase + (size_t)nb) * 16 + jj];
        }

        {
            const int myp = (lane < 16) ? p0 : p1;
            const int krow = lane & 15;
            float cx = xyz[(size_t)myp * 3 + 0];
            float cy = xyz[(size_t)myp * 3 + 1];
            float cz = xyz[(size_t)myp * 3 + 2];
            size_t nb = bbase + (size_t)idx;
            float nx = xyz[nb * 3 + 0], ny = xyz[nb * 3 + 1], nz = xyz[nb * 3 + 2];
            float rx = cx - nx, ry = cy - ny, rz = cz - nz;
            float d = sqrtf(rx * rx + ry * ry + rz * rz);
            __half2* rp = (lane < 16) ? rp0 : rp1;
            __half2 z = __floats2half2_rn(0.f, 0.f);
            rp[krow * RP2 + 0] = __floats2half2_rn(d, rx);
            rp[krow * RP2 + 1] = __floats2half2_rn(ry, rz);
            rp[krow * RP2 + 2] = __floats2half2_rn(cx, cy);
            rp[krow * RP2 + 3] = __floats2half2_rn(cz, nx);
            rp[krow * RP2 + 4] = __floats2half2_rn(ny, nz);
            rp[krow * RP2 + 5] = z;
            rp[krow * RP2 + 6] = z;
            rp[krow * RP2 + 7] = z;
        }

        // idx dead now -- prefetch next iteration's neighbor row
        {
            int ppn = pp + nwarps;
            if (ppn < PHALF) idx = neigh[(size_t)(2 * ppn) * KNN + lane];
        }
        __syncwarp();

        // lfa1 via f16 mma (K=16 covers all 10 rows), B shared
        {
            unsigned a00 = rp0w[gid * RP2 + tig];
            unsigned a01 = rp0w[(gid + 8) * RP2 + tig];
            unsigned a02 = rp0w[gid * RP2 + tig + 4];
            unsigned a03 = rp0w[(gid + 8) * RP2 + tig + 4];
            unsigned a10 = rp1w[gid * RP2 + tig];
            unsigned a11 = rp1w[(gid + 8) * RP2 + tig];
            unsigned a12 = rp1w[gid * RP2 + tig + 4];
            unsigned a13 = rp1w[(gid + 8) * RP2 + tig + 4];
            float ac0[4][4], ac1[4][4];
            #pragma unroll
            for (int n = 0; n < 4; n++)
                #pragma unroll
                for (int j = 0; j < 4; j++) { ac0[n][j] = 0.f; ac1[n][j] = 0.f; }
            const uint2* br = s_wl1p + tig * WH32 + gid;
            #pragma unroll
            for (int n = 0; n < 4; n++) {
                uint2 bb = br[8 * n];
                mma_f16(ac0[n], a00, a01, a02, a03, bb.x, bb.y);
                mma_f16(ac1[n], a10, a11, a12, a13, bb.x, bb.y);
            }
            #pragma unroll
            for (int n = 0; n < 4; n++) {
                int c0 = n * 8 + 2 * tig;
                float b0 = s_vec[c0], b1 = s_vec[c0 + 1];
                fs0_h[gid * FS_H2 + 16 + n * 4 + tig] =
                    __floats2half2_rn(fmaxf(ac0[n][0] + b0, 0.f), fmaxf(ac0[n][1] + b1, 0.f));
                fs0_h[(gid + 8) * FS_H2 + 16 + n * 4 + tig] =
                    __floats2half2_rn(fmaxf(ac0[n][2] + b0, 0.f), fmaxf(ac0[n][3] + b1, 0.f));
                fs1_h[gid * FS_H2 + 16 + n * 4 + tig] =
                    __floats2half2_rn(fmaxf(ac1[n][0] + b0, 0.f), fmaxf(ac1[n][1] + b1, 0.f));
                fs1_h[(gid + 8) * FS_H2 + 16 + n * 4 + tig] =
                    __floats2half2_rn(fmaxf(ac1[n][2] + b0, 0.f), fmaxf(ac1[n][3] + b1, 0.f));
            }
        }
        __syncwarp();

        // logits mma -> exp -> fp16 weight tiles (overwrites rp -- dead)
        logits_exp_x2(fsw0, fsw1, elg0, elg1, s_wfcp, lane);
        __syncwarp();
        *(float2*)(agg_s + 2 * lane)      = att_pool_e2(elg0, fs0_h, lane);
        *(float2*)(agg_s + 64 + 2 * lane) = att_pool_e2(elg1, fs1_h, lane);
        __syncwarp();

        // f_agg for both points, wam read once; fp16 packed write
        {
            float acc0 = 0.f, acc1 = 0.f;
            #pragma unroll
            for (int d2 = 0; d2 < 32; d2 += 2) {
                float4 a0 = *(const float4*)(agg_s + 2 * d2);
                float4 a1 = *(const float4*)(agg_s + 64 + 2 * d2);
                float2 w0 = s_wamp[d2 * 32 + lane];
                float2 w1 = s_wamp[(d2 + 1) * 32 + lane];
                acc0 += a0.x * w0.x + a0.y * w0.y + a0.z * w1.x + a0.w * w1.y;
                acc1 += a1.x * w0.x + a1.y * w0.y + a1.z * w1.x + a1.w * w1.y;
            }
            float bb = s_vec[64 + lane];
            float o0 = fmaxf(acc0 + bb, 0.f);
            float o1 = fmaxf(acc1 + bb, 0.f);
            float o0x = __shfl_xor_sync(0xffffffffu, o0, 1);
            float o1x = __shfl_xor_sync(0xffffffffu, o1, 1);
            if (!(lane & 1)) {
                fah[(size_t)p0 * 16 + (lane >> 1)] = f2_to_u(o0, o0x);
                fah[(size_t)p1 * 16 + (lane >> 1)] = f2_to_u(o1, o1x);
            }
        }

        // lfa2 via f16 mma, B shared -> g_fx2
        {
            float ac0[4][4], ac1[4][4];
            #pragma unroll
            for (int n = 0; n < 4; n++)
                #pragma unroll
                for (int j = 0; j < 4; j++) { ac0[n][j] = 0.f; ac1[n][j] = 0.f; }
            #pragma unroll
            for (int q = 0; q < 2; q++) {
                unsigned a00 = fsw0[gid * FS_H2 + 16 + q * 8 + tig];
                unsigned a01 = fsw0[(gid + 8) * FS_H2 + 16 + q * 8 + tig];
                unsigned a02 = fsw0[gid * FS_H2 + 16 + q * 8 + tig + 4];
                unsigned a03 = fsw0[(gid + 8) * FS_H2 + 16 + q * 8 + tig + 4];
                unsigned a10 = fsw1[gid * FS_H2 + 16 + q * 8 + tig];
                unsigned a11 = fsw1[(gid + 8) * FS_H2 + 16 + q * 8 + tig];
                unsigned a12 = fsw1[gid * FS_H2 + 16 + q * 8 + tig + 4];
                unsigned a13 = fsw1[(gid + 8) * FS_H2 + 16 + q * 8 + tig + 4];
                const uint2* br = s_wl2p + (q * 4 + tig) * WH32 + gid;
                #pragma unroll
                for (int n = 0; n < 4; n++) {
                    uint2 bb = br[8 * n];
                    mma_f16(ac0[n], a00, a01, a02, a03, bb.x, bb.y);
                    mma_f16(ac1[n], a10, a11, a12, a13, bb.x, bb.y);
                }
            }
            #pragma unroll
            for (int n = 0; n < 4; n++) {
                int c0 = n * 8 + 2 * tig;
                float b0 = s_vec[32 + c0], b1 = s_vec[32 + c0 + 1];
                g_fx2[((size_t)p0 * KNN + gid) * 16 + (c0 >> 1)] =
                    __floats2half2_rn(fmaxf(ac0[n][0] + b0, 0.f), fmaxf(ac0[n][1] + b1, 0.f));
                g_fx2[((size_t)p0 * KNN + gid + 8) * 16 + (c0 >> 1)] =
                    __floats2half2_rn(fmaxf(ac0[n][2] + b0, 0.f), fmaxf(ac0[n][3] + b1, 0.f));
                g_fx2[((size_t)p1 * KNN + gid) * 16 + (c0 >> 1)] =
                    __floats2half2_rn(fmaxf(ac1[n][0] + b0, 0.f), fmaxf(ac1[n][1] + b1, 0.f));
                g_fx2[((size_t)p1 * KNN + gid + 8) * 16 + (c0 >> 1)] =
                    __floats2half2_rn(fmaxf(ac1[n][2] + b0, 0.f), fmaxf(ac1[n][3] + b1, 0.f));
            }
        }
        __syncwarp();
    }
}

// ---------------------------------------------------------------------------
// Kernel 3: TWO points per warp: prefetched idx + fx2 regs; fp16 gather +
//           logits->exp + pools -> g_agg2.  23 warps.
// ---------------------------------------------------------------------------
#define K3_WARP_FLOATS 2304
#define K3_BASE_FLOATS 2176
#define K3_WARPS 23
#define K3_SMEM_BYTES ((K3_BASE_FLOATS + K3_WARPS * K3_WARP_FLOATS) * 4)

__global__ __launch_bounds__(736) void kern_att2(
    const int* __restrict__ neigh,
    const float* __restrict__ wfc2)
{
    extern __shared__ float sm[];
    uint2* s_wfcp = (uint2*)sm;               // [16][68] uint2
    float* s_wrp  = sm + K3_BASE_FLOATS;

    for (int i = threadIdx.x; i < 1024; i += blockDim.x) {
        int r = i >> 6, c = i & 63;
        int q = r >> 2, t = r & 3;
        int k0 = 16 * q + 2 * t;
        s_wfcp[r * WH64 + c] = make_uint2(
            f2_to_u(wfc2[k0 * 64 + c], wfc2[(k0 + 1) * 64 + c]),
            f2_to_u(wfc2[(k0 + 8) * 64 + c], wfc2[(k0 + 9) * 64 + c]));
    }
    __syncthreads();

    const int lane = threadIdx.x & 31;
    const int warp = threadIdx.x >> 5;
    float* wbase = s_wrp + warp * K3_WARP_FLOATS;
    __half2*  fs0_h = (__half2*)wbase;
    __half2*  fs1_h = (__half2*)(wbase + 576);
    unsigned* fsw0  = (unsigned*)fs0_h;
    unsigned* fsw1  = (unsigned*)fs1_h;
    __half2*  elg0  = (__half2*)(wbase + 1152);
    __half2*  elg1  = (__half2*)(wbase + 1728);

    const int kk = lane >> 4;
    const int jj = lane & 15;

    const unsigned* fah = (const unsigned*)g_f_agg_h;

    const int nwarps = (gridDim.x * blockDim.x) >> 5;
    int gw = (blockIdx.x * blockDim.x + threadIdx.x) >> 5;

    // prefetch first iteration's idx and fx2 rows (addresses deterministic)
    int idx = 0;
    unsigned pf0[8], pf1[8];
    if (gw < PHALF) {
        idx = neigh[(size_t)(2 * gw) * KNN + lane];
        const unsigned* s0 = (const unsigned*)(g_fx2 + (size_t)(2 * gw) * KNN * 16);
        const unsigned* s1 = (const unsigned*)(g_fx2 + (size_t)(2 * gw + 1) * KNN * 16);
        #pragma unroll
        for (int k = 0; k < KNN; k += 2) {
            pf0[k >> 1] = s0[(k + kk) * 16 + jj];
            pf1[k >> 1] = s1[(k + kk) * 16 + jj];
        }
    }

    for (int pp = gw; pp < PHALF; pp += nwarps) {
        const int p0 = 2 * pp;
        const int b = p0 / NPTS;
        const size_t bbase = (size_t)b * NPTS;

        // store prefetched fx2 into fs tiles
        #pragma unroll
        for (int k = 0; k < KNN; k += 2) {
            fsw0[(k + kk) * FS_H2 + 16 + jj] = pf0[k >> 1];
            fsw1[(k + kk) * FS_H2 + 16 + jj] = pf1[k >> 1];
        }

        // gather via prefetched idx
        #pragma unroll
        for (int k = 0; k < KNN; k += 2) {
            int nb = __shfl_sync(0xffffffffu, idx, k + kk);
            fsw0[(k + kk) * FS_H2 + jj] = fah[(bbase + (size_t)nb) * 16 + jj];
        }
        #pragma unroll
        for (int k = 0; k < KNN; k += 2) {
            int nb = __shfl_sync(0xffffffffu, idx, 16 + k + kk);
            fsw1[(k + kk) * FS_H2 + jj] = fah[(bbase + (size_t)nb) * 16 + jj];
        }

        // prefetch next iteration (independent addresses)
        {
            int ppn = pp + nwarps;
            if (ppn < PHALF) {
                idx = neigh[(size_t)(2 * ppn) * KNN + lane];
                const unsigned* s0 = (const unsigned*)(g_fx2 + (size_t)(2 * ppn) * KNN * 16);
                const unsigned* s1 = (const unsigned*)(g_fx2 + (size_t)(2 * ppn + 1) * KNN * 16);
                #pragma unroll
                for (int k = 0; k < KNN; k += 2) {
                    pf0[k >> 1] = s0[(k + kk) * 16 + jj];
                    pf1[k >> 1] = s1[(k + kk) * 16 + jj];
                }
            }
        }
        __syncwarp();

        logits_exp_x2(fsw0, fsw1, elg0, elg1, s_wfcp, lane);
        __syncwarp();

        *(float2*)(&g_agg2[(size_t)p0 * 64 + 2 * lane])       = att_pool_e2(elg0, fs0_h, lane);
        *(float2*)(&g_agg2[(size_t)(p0 + 1) * 64 + 2 * lane]) = att_pool_e2(elg1, fs1_h, lane);
        __syncwarp();
    }
}

// ---------------------------------------------------------------------------
// Kernel 4: 16-point tiles, SINGLE TF32 GEMMs; GEMM2 n-halves merged so
//           A-fragments load once.  18 warps.
// ---------------------------------------------------------------------------
#define OUT_WARPS 18
#define OUT_BASE_FLOATS 17216
#define OUT_WARP_FLOATS 1600
#define OUT_SMEM_BYTES ((OUT_BASE_FLOATS + OUT_WARPS * OUT_WARP_FLOATS) * 4)

__global__ __launch_bounds__(576) void kern_out(
    const float* __restrict__ feature,
    const float* __restrict__ wam2, const float* __restrict__ sam2, const float* __restrict__ bam2,
    const float* __restrict__ wmlp2, const float* __restrict__ smlp2, const float* __restrict__ bmlp2,
    const float* __restrict__ wsc, const float* __restrict__ ssc, const float* __restrict__ bsc,
    float* __restrict__ out)
{
    extern __shared__ float sm[];
    float2* w1p  = (float2*)sm;              // [32][68] float2 = 4352 floats
    float2* w23p = (float2*)(sm + 4352);     // [48][132] float2 = 12672 floats
    float*  b1   = sm + 17024;               // [64]
    float*  b2   = sm + 17088;               // [128]
    float*  wrp  = sm + OUT_BASE_FLOATS;

    for (int i = threadIdx.x; i < 2048; i += blockDim.x) {
        int r = i >> 6, c = i & 63;
        int k0 = (r >> 2) * 8 + (r & 3), k1 = k0 + 4;
        w1p[r * P2F64 + c] = make_float2(to_tf32(wam2[k0 * 64 + c] * sam2[c]),
                                         to_tf32(wam2[k1 * 64 + c] * sam2[c]));
    }
    for (int i = threadIdx.x; i < 6144; i += blockDim.x) {
        int r = i >> 7, c = i & 127;
        int k0 = (r >> 2) * 8 + (r & 3), k1 = k0 + 4;
        float v0 = (k0 < 64) ? wmlp2[k0 * 128 + c] * smlp2[c] : wsc[(k0 - 64) * 128 + c] * ssc[c];
        float v1 = (k1 < 64) ? wmlp2[k1 * 128 + c] * smlp2[c] : wsc[(k1 - 64) * 128 + c] * ssc[c];
        w23p[r * P2F128 + c] = make_float2(to_tf32(v0), to_tf32(v1));
    }
    if (threadIdx.x < 64)  b1[threadIdx.x] = bam2[threadIdx.x];
    if (threadIdx.x < 128) b2[threadIdx.x] = bmlp2[threadIdx.x] + bsc[threadIdx.x];
    __syncthreads();

    const int lane = threadIdx.x & 31;
    const int warp = threadIdx.x >> 5;
    const int gid = lane >> 2, tig = lane & 3;
    float* A1 = wrp + warp * OUT_WARP_FLOATS;  // [16][100]

    const int nwarps = (gridDim.x * blockDim.x) >> 5;
    int gw = (blockIdx.x * blockDim.x + threadIdx.x) >> 5;
    const int ntiles = P_TOTAL / 16;

    for (int t = gw; t < ntiles; t += nwarps) {
        const int p0 = t * 16;

        #pragma unroll
        for (int r = 0; r < 16; r++) {
            A1[r * OA_PAD + lane]      = g_agg2[(size_t)(p0 + r) * 64 + lane];
            A1[r * OA_PAD + 32 + lane] = g_agg2[(size_t)(p0 + r) * 64 + 32 + lane];
            A1[r * OA_PAD + 64 + lane] = feature[(size_t)(p0 + r) * 32 + lane];
        }
        __syncwarp();

        // GEMM1 (single tf32): pc2 = relu(agg @ w1 + b1) -> A cols 0..63
        {
            float acc[8][4];
            #pragma unroll
            for (int n = 0; n < 8; n++) { acc[n][0]=0.f; acc[n][1]=0.f; acc[n][2]=0.f; acc[n][3]=0.f; }
            #pragma unroll
            for (int q = 0; q < 8; q++) {
                unsigned a0 = __float_as_uint(to_tf32(A1[gid * OA_PAD + q * 8 + tig]));
                unsigned a1 = __float_as_uint(to_tf32(A1[(gid + 8) * OA_PAD + q * 8 + tig]));
                unsigned a2 = __float_as_uint(to_tf32(A1[gid * OA_PAD + q * 8 + tig + 4]));
                unsigned a3 = __float_as_uint(to_tf32(A1[(gid + 8) * OA_PAD + q * 8 + tig + 4]));
                const float2* br = w1p + (q * 4 + tig) * P2F64 + gid;
                #pragma unroll
                for (int n = 0; n < 8; n++) {
                    float2 b = br[8 * n];
                    mma_tf32(acc[n], a0, a1, a2, a3,
                             __float_as_uint(b.x), __float_as_uint(b.y));
                }
            }
            __syncwarp();
            #pragma unroll
            for (int n = 0; n < 8; n++) {
                int c0 = n * 8 + 2 * tig;
                float bb0 = b1[c0], bb1 = b1[c0 + 1];
                *(float2*)(A1 + gid * OA_PAD + c0) =
                    make_float2(fmaxf(acc[n][0] + bb0, 0.f), fmaxf(acc[n][1] + bb1, 0.f));
                *(float2*)(A1 + (gid + 8) * OA_PAD + c0) =
                    make_float2(fmaxf(acc[n][2] + bb0, 0.f), fmaxf(acc[n][3] + bb1, 0.f));
            }
        }
        __syncwarp();

        // GEMM2 (single tf32, merged n-halves): out = leaky(A[16][96] @ w23 + b2)
        {
            float acc[16][4];
            #pragma unroll
            for (int m = 0; m < 16; m++)
                #pragma unroll
                for (int j = 0; j < 4; j++) acc[m][j] = 0.f;
            #pragma unroll
            for (int q = 0; q < 12; q++) {
                unsigned a0 = __float_as_uint(to_tf32(A1[gid * OA_PAD + q * 8 + tig]));
                unsigned a1 = __float_as_uint(to_tf32(A1[(gid + 8) * OA_PAD + q * 8 + tig]));
                unsigned a2 = __float_as_uint(to_tf32(A1[gid * OA_PAD + q * 8 + tig + 4]));
                unsigned a3 = __float_as_uint(to_tf32(A1[(gid + 8) * OA_PAD + q * 8 + tig + 4]));
                const float2* br = w23p + (q * 4 + tig) * P2F128 + gid;
                #pragma unroll
                for (int m = 0; m < 16; m++) {
                    int off = (m >> 3) * 64 + (m & 7) * 8;
                    float2 b = br[off];
                    mma_tf32(acc[m], a0, a1, a2, a3,
                             __float_as_uint(b.x), __float_as_uint(b.y));
                }
            }
            #pragma unroll
            for (int m = 0; m < 16; m++) {
                int c0 = (m >> 3) * 64 + (m & 7) * 8 + 2 * tig;
                float bb0 = b2[c0], bb1 = b2[c0 + 1];
                float v0 = acc[m][0] + bb0; v0 = (v0 < 0.f) ? 0.2f * v0 : v0;
                float v1 = acc[m][1] + bb1; v1 = (v1 < 0.f) ? 0.2f * v1 : v1;
                float v2 = acc[m][2] + bb0; v2 = (v2 < 0.f) ? 0.2f * v2 : v2;
                float v3 = acc[m][3] + bb1; v3 = (v3 < 0.f) ? 0.2f * v3 : v3;
                *(float2*)(&out[(size_t)(p0 + gid) * 128 + c0])     = make_float2(v0, v1);
                *(float2*)(&out[(size_t)(p0 + gid + 8) * 128 + c0]) = make_float2(v2, v3);
            }
        }
        __syncwarp();
    }
}

// ---------------------------------------------------------------------------
extern "C" void kernel_launch(void* const* d_in, const int* in_sizes, int n_in,
                              void* d_out, int out_size)
{
    const float* feature = (const float*)d_in[0];
    const float* xyz     = (const float*)d_in[1];
    const int*   neigh   = (const int*)  d_in[2];
    const float* w_mlp1  = (const float*)d_in[3];
    const float* s_mlp1  = (const float*)d_in[4];
    const float* b_mlp1  = (const float*)d_in[5];
    const float* w_lfa1  = (const float*)d_in[6];
    const float* s_lfa1  = (const float*)d_in[7];
    const float* b_lfa1  = (const float*)d_in[8];
    const float* w_fc1   = (const float*)d_in[9];
    const float* w_am1   = (const float*)d_in[10];
    const float* s_am1   = (const float*)d_in[11];
    const float* b_am1   = (const float*)d_in[12];
    const float* w_lfa2  = (const float*)d_in[13];
    const float* s_lfa2  = (const float*)d_in[14];
    const float* b_lfa2  = (const float*)d_in[15];
    const float* w_fc2   = (const float*)d_in[16];
    const float* w_am2   = (const float*)d_in[17];
    const float* s_am2   = (const float*)d_in[18];
    const float* b_am2   = (const float*)d_in[19];
    const float* w_mlp2  = (const float*)d_in[20];
    const float* s_mlp2  = (const float*)d_in[21];
    const float* b_mlp2  = (const float*)d_in[22];
    const float* w_sc    = (const float*)d_in[23];
    const float* s_sc    = (const float*)d_in[24];
    const float* b_sc    = (const float*)d_in[25];
    float* out = (float*)d_out;

    cudaFuncSetAttribute(kern_att1, cudaFuncAttributeMaxDynamicSharedMemorySize, K2_SMEM_BYTES);
    cudaFuncSetAttribute(kern_att2, cudaFuncAttributeMaxDynamicSharedMemorySize, K3_SMEM_BYTES);
    cudaFuncSetAttribute(kern_out,  cudaFuncAttributeMaxDynamicSharedMemorySize, OUT_SMEM_BYTES);

    kern_mlp1<<<2048, 256>>>(feature, w_mlp1, s_mlp1, b_mlp1);

    kern_att1<<<148, 640, K2_SMEM_BYTES>>>(
        xyz, neigh,
        w_lfa1, s_lfa1, b_lfa1,
        w_fc1,
        w_am1, s_am1, b_am1,
        w_lfa2, s_lfa2, b_lfa2);

    kern_att2<<<148, 736, K3_SMEM_BYTES>>>(neigh, w_fc2);

    kern_out<<<148, 576, OUT_SMEM_BYTES>>>(
        feature,
        w_am2, s_am2, b_am2,
        w_mlp2, s_mlp2, b_mlp2,
        w_sc, s_sc, b_sc,
        out);
}

// round 17
// speedup vs baseline: 1.0438x; 1.0438x over previous
#include <cuda_runtime.h>
#include <cuda_fp16.h>
#include <math.h>

#define BATCH 4
#define NPTS  40960
#define KNN   16
#define P_TOTAL (BATCH * NPTS)   // 163840
#define PHALF  (P_TOTAL / 2)

#define FS_H2  36    // fs/elg tile row stride in half2 units (4 mod 32)
#define WH64   68    // fp16 B-tile stride, 64 cols, uint2 units
#define WH32   36    // fp16 B-tile stride, 32 cols, uint2 units
#define P2F64  68    // float2 B-tile stride, 64 cols (4 mod 16)
#define P2F128 132   // float2 B-tile stride, 128 cols (4 mod 16)
#define RP2    12    // relpos tile stride in half2 units
#define OA_PAD 100   // kern_out A tile stride (4 mod 32)

// Scratch (device globals) -- gathered tensors stored pre-packed fp16
__device__ __half2 g_f_pc_h [P_TOTAL * 16];                  // 10.5 MB
__device__ __half2 g_f_agg_h[P_TOTAL * 16];                  // 10.5 MB
__device__ float   g_agg2 [(size_t)P_TOTAL * 64];            // 42 MB
__device__ __half2 g_fx2  [(size_t)P_TOTAL * KNN * 16];      // 168 MB

__device__ __forceinline__ float to_tf32(float x) {
    float r;
    asm("cvt.rna.tf32.f32 %0, %1;" : "=f"(r) : "f"(x));
    return r;
}
__device__ __forceinline__ unsigned f2_to_u(float a, float b) {
    __half2 h = __floats2half2_rn(a, b);
    return *(unsigned*)&h;
}

__device__ __forceinline__ void mma_tf32(float* c,
                                         unsigned a0, unsigned a1, unsigned a2, unsigned a3,
                                         unsigned b0, unsigned b1) {
    asm("mma.sync.aligned.m16n8k8.row.col.f32.tf32.tf32.f32 "
        "{%0,%1,%2,%3}, {%4,%5,%6,%7}, {%8,%9}, {%0,%1,%2,%3};"
        : "+f"(c[0]), "+f"(c[1]), "+f"(c[2]), "+f"(c[3])
        : "r"(a0), "r"(a1), "r"(a2), "r"(a3), "r"(b0), "r"(b1));
}
__device__ __forceinline__ void mma_f16(float* c,
                                        unsigned a0, unsigned a1, unsigned a2, unsigned a3,
                                        unsigned b0, unsigned b1) {
    asm("mma.sync.aligned.m16n8k16.row.col.f32.f16.f16.f32 "
        "{%0,%1,%2,%3}, {%4,%5,%6,%7}, {%8,%9}, {%0,%1,%2,%3};"
        : "+f"(c[0]), "+f"(c[1]), "+f"(c[2]), "+f"(c[3])
        : "r"(a0), "r"(a1), "r"(a2), "r"(a3), "r"(b0), "r"(b1));
}

// dual-point logits -> exp(logit-8) stored as fp16 weight tiles (elg).
__device__ __forceinline__ void logits_exp_x2(const unsigned* __restrict__ fsw0,
                                              const unsigned* __restrict__ fsw1,
                                              __half2* __restrict__ elg0,
                                              __half2* __restrict__ elg1,
                                              const uint2* __restrict__ wfc, int lane)
{
    const int gid = lane >> 2;
    const int tig = lane & 3;
    float ac0[8][4], ac1[8][4];
    #pragma unroll
    for (int n = 0; n < 8; n++)
        #pragma unroll
        for (int j = 0; j < 4; j++) { ac0[n][j] = 0.f; ac1[n][j] = 0.f; }
    #pragma unroll
    for (int q = 0; q < 4; q++) {
        unsigned a00 = fsw0[gid * FS_H2 + q * 8 + tig];
        unsigned a01 = fsw0[(gid + 8) * FS_H2 + q * 8 + tig];
        unsigned a02 = fsw0[gid * FS_H2 + q * 8 + tig + 4];
        unsigned a03 = fsw0[(gid + 8) * FS_H2 + q * 8 + tig + 4];
        unsigned a10 = fsw1[gid * FS_H2 + q * 8 + tig];
        unsigned a11 = fsw1[(gid + 8) * FS_H2 + q * 8 + tig];
        unsigned a12 = fsw1[gid * FS_H2 + q * 8 + tig + 4];
        unsigned a13 = fsw1[(gid + 8) * FS_H2 + q * 8 + tig + 4];
        const uint2* br = wfc + (q * 4 + tig) * WH64 + gid;
        #pragma unroll
        for (int n = 0; n < 8; n++) {
            uint2 b = br[8 * n];
            mma_f16(ac0[n], a00, a01, a02, a03, b.x, b.y);
            mma_f16(ac1[n], a10, a11, a12, a13, b.x, b.y);
        }
    }
    #pragma unroll
    for (int n = 0; n < 8; n++) {
        elg0[gid * FS_H2 + n * 4 + tig] =
            __floats2half2_rn(__expf(ac0[n][0] - 8.f), __expf(ac0[n][1] - 8.f));
        elg0[(gid + 8) * FS_H2 + n * 4 + tig] =
            __floats2half2_rn(__expf(ac0[n][2] - 8.f), __expf(ac0[n][3] - 8.f));
        elg1[gid * FS_H2 + n * 4 + tig] =
            __floats2half2_rn(__expf(ac1[n][0] - 8.f), __expf(ac1[n][1] - 8.f));
        elg1[(gid + 8) * FS_H2 + n * 4 + tig] =
            __floats2half2_rn(__expf(ac1[n][2] - 8.f), __expf(ac1[n][3] - 8.f));
    }
}

// Pool for channel pair (2*lane, 2*lane+1): conflict-free half2 loads.
__device__ __forceinline__ float2 att_pool_e2(const __half2* __restrict__ elg,
                                              const __half2* __restrict__ fs_h, int lane)
{
    float sx0 = 0.f, ax0 = 0.f, sx1 = 0.f, ax1 = 0.f;
    float sy0 = 0.f, ay0 = 0.f, sy1 = 0.f, ay1 = 0.f;
    #pragma unroll
    for (int k = 0; k < KNN; k += 2) {
        float2 e0 = __half22float2(elg[k * FS_H2 + lane]);
        float2 v0 = __half22float2(fs_h[k * FS_H2 + lane]);
        float2 e1 = __half22float2(elg[(k + 1) * FS_H2 + lane]);
        float2 v1 = __half22float2(fs_h[(k + 1) * FS_H2 + lane]);
        sx0 += e0.x; ax0 += e0.x * v0.x;
        sy0 += e0.y; ay0 += e0.y * v0.y;
        sx1 += e1.x; ax1 += e1.x * v1.x;
        sy1 += e1.y; ay1 += e1.y * v1.y;
    }
    return make_float2(__fdividef(ax0 + ax1, sx0 + sx1),
                       __fdividef(ay0 + ay1, sy0 + sy1));
}

// ---------------------------------------------------------------------------
// Kernel 1: f_pc = ReLU((feature @ w_mlp1) * s + b) -> fp16 packed
// ---------------------------------------------------------------------------
__global__ __launch_bounds__(256) void kern_mlp1(
    const float* __restrict__ feature,
    const float* __restrict__ w, const float* __restrict__ s, const float* __restrict__ b)
{
    __shared__ float xs[8][32];

    const int lane = threadIdx.x & 31;
    const int warp = threadIdx.x >> 5;

    float wcol[32];
    #pragma unroll
    for (int j = 0; j < 32; j++) wcol[j] = w[j * 32 + lane];
    const float sv = s[lane];
    const float bv = b[lane];

    unsigned* dst = (unsigned*)g_f_pc_h;

    const int nwarps = (gridDim.x * blockDim.x) >> 5;
    int gw = (blockIdx.x * blockDim.x + threadIdx.x) >> 5;

    for (int p = gw; p < P_TOTAL; p += nwarps) {
        xs[warp][lane] = feature[(size_t)p * 32 + lane];
        __syncwarp();
        float acc = 0.f;
        #pragma unroll
        for (int j4 = 0; j4 < 32; j4 += 4) {
            float4 f = *(const float4*)(&xs[warp][j4]);
            acc += f.x * wcol[j4] + f.y * wcol[j4 + 1]
                 + f.z * wcol[j4 + 2] + f.w * wcol[j4 + 3];
        }
        float o = fmaxf(acc * sv + bv, 0.f);
        float o1 = __shfl_xor_sync(0xffffffffu, o, 1);
        if (!(lane & 1))
            dst[(size_t)p * 16 + (lane >> 1)] = f2_to_u(o, o1);
        __syncwarp();
    }
}

// ---------------------------------------------------------------------------
// Kernel 2: TWO points per warp. idx-prefetch (1 reg); rel_pos + lfa1(f16) +
//           direct fp16 gather + logits->exp + pool + f_agg ; lfa2 -> g_fx2.
// ---------------------------------------------------------------------------
#define K2_WARP_FLOATS 2432
#define K2_BASE_FLOATS 5216
#define K2_WARPS 20
#define K2_SMEM_BYTES ((K2_BASE_FLOATS + K2_WARPS * K2_WARP_FLOATS) * 4)

__global__ __launch_bounds__(640) void kern_att1(
    const float* __restrict__ xyz, const int* __restrict__ neigh,
    const float* __restrict__ wlfa1, const float* __restrict__ slfa1, const float* __restrict__ blfa1,
    const float* __restrict__ wfc1,
    const float* __restrict__ wam1, const float* __restrict__ sam1, const float* __restrict__ bam1,
    const float* __restrict__ wlfa2, const float* __restrict__ slfa2, const float* __restrict__ blfa2)
{
    extern __shared__ float sm[];
    uint2*  s_wfcp = (uint2*)sm;              // [16][68] uint2 = 2176 floats
    float2* s_wamp = (float2*)(sm + 2176);    // [32][32] float2 = 2048 floats
    uint2*  s_wl1p = (uint2*)(sm + 4224);     // [4][36] uint2 = 288 floats
    uint2*  s_wl2p = (uint2*)(sm + 4512);     // [8][36] uint2 = 576 floats
    float*  s_vec  = sm + 5088;               // 128: blfa1, blfa2, bam1
    float*  s_wrp  = sm + K2_BASE_FLOATS;

    for (int i = threadIdx.x; i < 1024; i += blockDim.x) {
        int r = i >> 6, c = i & 63;
        int q = r >> 2, t = r & 3;
        int k0 = 16 * q + 2 * t;
        s_wfcp[r * WH64 + c] = make_uint2(
            f2_to_u(wfc1[k0 * 64 + c], wfc1[(k0 + 1) * 64 + c]),
            f2_to_u(wfc1[(k0 + 8) * 64 + c], wfc1[(k0 + 9) * 64 + c]));
    }
    for (int i = threadIdx.x; i < 1024; i += blockDim.x) {
        int r = i >> 5, c = i & 31;
        s_wamp[r * 32 + c] = make_float2(wam1[(2 * r) * 32 + c] * sam1[c],
                                         wam1[(2 * r + 1) * 32 + c] * sam1[c]);
    }
    for (int i = threadIdx.x; i < 128; i += blockDim.x) {
        int t = i >> 5, c = i & 31;
        int k0 = 2 * t, k1 = 2 * t + 8;
        float w00 = wlfa1[k0 * 32 + c] * slfa1[c];
        float w01 = wlfa1[(k0 + 1) * 32 + c] * slfa1[c];
        float w10 = (k1 < 10) ? wlfa1[k1 * 32 + c] * slfa1[c] : 0.f;
        float w11 = (k1 + 1 < 10) ? wlfa1[(k1 + 1) * 32 + c] * slfa1[c] : 0.f;
        s_wl1p[t * WH32 + c] = make_uint2(f2_to_u(w00, w01), f2_to_u(w10, w11));
    }
    for (int i = threadIdx.x; i < 256; i += blockDim.x) {
        int r = i >> 5, c = i & 31;
        int q = r >> 2, t = r & 3;
        int k0 = 16 * q + 2 * t;
        s_wl2p[r * WH32 + c] = make_uint2(
            f2_to_u(wlfa2[k0 * 32 + c] * slfa2[c], wlfa2[(k0 + 1) * 32 + c] * slfa2[c]),
            f2_to_u(wlfa2[(k0 + 8) * 32 + c] * slfa2[c], wlfa2[(k0 + 9) * 32 + c] * slfa2[c]));
    }
    if (threadIdx.x < 32) {
        int l = threadIdx.x;
        s_vec[l]      = blfa1[l];
        s_vec[32 + l] = blfa2[l];
        s_vec[64 + l] = bam1[l];
    }
    __syncthreads();

    const int lane = threadIdx.x & 31;
    const int warp = threadIdx.x >> 5;
    const int gid = lane >> 2, tig = lane & 3;
    const int kk = lane >> 4, jj = lane & 15;
    float* wbase = s_wrp + warp * K2_WARP_FLOATS;
    __half2*  fs0_h = (__half2*)wbase;            // [16][36] half2
    __half2*  fs1_h = (__half2*)(wbase + 576);
    unsigned* fsw0  = (unsigned*)fs0_h;
    unsigned* fsw1  = (unsigned*)fs1_h;
    __half2*  elg0  = (__half2*)(wbase + 1152);   // [16][36] half2 (weights)
    __half2*  elg1  = (__half2*)(wbase + 1728);
    __half2*  rp0   = elg0;                       // relpos aliases elg (dead)
    __half2*  rp1   = elg1;
    unsigned* rp0w  = (unsigned*)rp0;
    unsigned* rp1w  = (unsigned*)rp1;
    float* agg_s = wbase + 2304;                  // [128]

    const unsigned* pc = (const unsigned*)g_f_pc_h;
    unsigned* fah = (unsigned*)g_f_agg_h;

    const int nwarps = (gridDim.x * blockDim.x) >> 5;
    int gw = (blockIdx.x * blockDim.x + threadIdx.x) >> 5;

    // prefetch first iteration's neighbor row (1 register)
    int idx = (gw < PHALF) ? neigh[(size_t)(2 * gw) * KNN + lane] : 0;

    for (int pp = gw; pp < PHALF; pp += nwarps) {
        const int p0 = 2 * pp, p1 = p0 + 1;
        const int b = p0 / NPTS;
        const size_t bbase = (size_t)b * NPTS;

        // direct fp16 gather: 2 rows per pass, lane (kk,jj)
        #pragma unroll
        for (int k = 0; k < KNN; k += 2) {
            int nb = __shfl_sync(0xffffffffu, idx, k + kk);
            fsw0[(k + kk) * FS_H2 + jj] = pc[(bbase + (size_t)nb) * 16 + jj];
        }
        #pragma unroll
        for (int k = 0; k < KNN; k += 2) {
            int nb = __shfl_sync(0xffffffffu, idx, 16 + k + kk);
            fsw1[(k + kk) * FS_H2 + jj] = pc[(bbase + (size_t)nb) * 16 + jj];
        }

        {
            const int myp = (lane < 16) ? p0 : p1;
            const int krow = lane & 15;
            float cx = xyz[(size_t)myp * 3 + 0];
            float cy = xyz[(size_t)myp * 3 + 1];
            float cz = xyz[(size_t)myp * 3 + 2];
            size_t nb = bbase + (size_t)idx;
            float nx = xyz[nb * 3 + 0], ny = xyz[nb * 3 + 1], nz = xyz[nb * 3 + 2];
            float rx = cx - nx, ry = cy - ny, rz = cz - nz;
            float d = sqrtf(rx * rx + ry * ry + rz * rz);
            __half2* rp = (lane < 16) ? rp0 : rp1;
            __half2 z = __floats2half2_rn(0.f, 0.f);
            rp[krow * RP2 + 0] = __floats2half2_rn(d, rx);
            rp[krow * RP2 + 1] = __floats2half2_rn(ry, rz);
            rp[krow * RP2 + 2] = __floats2half2_rn(cx, cy);
            rp[krow * RP2 + 3] = __floats2half2_rn(cz, nx);
            rp[krow * RP2 + 4] = __floats2half2_rn(ny, nz);
            rp[krow * RP2 + 5] = z;
            rp[krow * RP2 + 6] = z;
            rp[krow * RP2 + 7] = z;
        }

        // idx dead now -- prefetch next iteration's neighbor row
        {
            int ppn = pp + nwarps;
            if (ppn < PHALF) idx = neigh[(size_t)(2 * ppn) * KNN + lane];
        }
        __syncwarp();

        // lfa1 via f16 mma (K=16 covers all 10 rows), B shared
        {
            unsigned a00 = rp0w[gid * RP2 + tig];
            unsigned a01 = rp0w[(gid + 8) * RP2 + tig];
            unsigned a02 = rp0w[gid * RP2 + tig + 4];
            unsigned a03 = rp0w[(gid + 8) * RP2 + tig + 4];
            unsigned a10 = rp1w[gid * RP2 + tig];
            unsigned a11 = rp1w[(gid + 8) * RP2 + tig];
            unsigned a12 = rp1w[gid * RP2 + tig + 4];
            unsigned a13 = rp1w[(gid + 8) * RP2 + tig + 4];
            float ac0[4][4], ac1[4][4];
            #pragma unroll
            for (int n = 0; n < 4; n++)
                #pragma unroll
                for (int j = 0; j < 4; j++) { ac0[n][j] = 0.f; ac1[n][j] = 0.f; }
            const uint2* br = s_wl1p + tig * WH32 + gid;
            #pragma unroll
            for (int n = 0; n < 4; n++) {
                uint2 bb = br[8 * n];
                mma_f16(ac0[n], a00, a01, a02, a03, bb.x, bb.y);
                mma_f16(ac1[n], a10, a11, a12, a13, bb.x, bb.y);
            }
            #pragma unroll
            for (int n = 0; n < 4; n++) {
                int c0 = n * 8 + 2 * tig;
                float b0 = s_vec[c0], b1 = s_vec[c0 + 1];
                fs0_h[gid * FS_H2 + 16 + n * 4 + tig] =
                    __floats2half2_rn(fmaxf(ac0[n][0] + b0, 0.f), fmaxf(ac0[n][1] + b1, 0.f));
                fs0_h[(gid + 8) * FS_H2 + 16 + n * 4 + tig] =
                    __floats2half2_rn(fmaxf(ac0[n][2] + b0, 0.f), fmaxf(ac0[n][3] + b1, 0.f));
                fs1_h[gid * FS_H2 + 16 + n * 4 + tig] =
                    __floats2half2_rn(fmaxf(ac1[n][0] + b0, 0.f), fmaxf(ac1[n][1] + b1, 0.f));
                fs1_h[(gid + 8) * FS_H2 + 16 + n * 4 + tig] =
                    __floats2half2_rn(fmaxf(ac1[n][2] + b0, 0.f), fmaxf(ac1[n][3] + b1, 0.f));
            }
        }
        __syncwarp();

        // logits mma -> exp -> fp16 weight tiles (overwrites rp -- dead)
        logits_exp_x2(fsw0, fsw1, elg0, elg1, s_wfcp, lane);
        __syncwarp();
        *(float2*)(agg_s + 2 * lane)      = att_pool_e2(elg0, fs0_h, lane);
        *(float2*)(agg_s + 64 + 2 * lane) = att_pool_e2(elg1, fs1_h, lane);
        __syncwarp();

        // f_agg for both points, wam read once; fp16 packed write
        {
            float acc0 = 0.f, acc1 = 0.f;
            #pragma unroll
            for (int d2 = 0; d2 < 32; d2 += 2) {
                float4 a0 = *(const float4*)(agg_s + 2 * d2);
                float4 a1 = *(const float4*)(agg_s + 64 + 2 * d2);
                float2 w0 = s_wamp[d2 * 32 + lane];
                float2 w1 = s_wamp[(d2 + 1) * 32 + lane];
                acc0 += a0.x * w0.x + a0.y * w0.y + a0.z * w1.x + a0.w * w1.y;
                acc1 += a1.x * w0.x + a1.y * w0.y + a1.z * w1.x + a1.w * w1.y;
            }
            float bb = s_vec[64 + lane];
            float o0 = fmaxf(acc0 + bb, 0.f);
            float o1 = fmaxf(acc1 + bb, 0.f);
            float o0x = __shfl_xor_sync(0xffffffffu, o0, 1);
            float o1x = __shfl_xor_sync(0xffffffffu, o1, 1);
            if (!(lane & 1)) {
                fah[(size_t)p0 * 16 + (lane >> 1)] = f2_to_u(o0, o0x);
                fah[(size_t)p1 * 16 + (lane >> 1)] = f2_to_u(o1, o1x);
            }
        }

        // lfa2 via f16 mma, B shared -> g_fx2
        {
            float ac0[4][4], ac1[4][4];
            #pragma unroll
            for (int n = 0; n < 4; n++)
                #pragma unroll
                for (int j = 0; j < 4; j++) { ac0[n][j] = 0.f; ac1[n][j] = 0.f; }
            #pragma unroll
            for (int q = 0; q < 2; q++) {
                unsigned a00 = fsw0[gid * FS_H2 + 16 + q * 8 + tig];
                unsigned a01 = fsw0[(gid + 8) * FS_H2 + 16 + q * 8 + tig];
                unsigned a02 = fsw0[gid * FS_H2 + 16 + q * 8 + tig + 4];
                unsigned a03 = fsw0[(gid + 8) * FS_H2 + 16 + q * 8 + tig + 4];
                unsigned a10 = fsw1[gid * FS_H2 + 16 + q * 8 + tig];
                unsigned a11 = fsw1[(gid + 8) * FS_H2 + 16 + q * 8 + tig];
                unsigned a12 = fsw1[gid * FS_H2 + 16 + q * 8 + tig + 4];
                unsigned a13 = fsw1[(gid + 8) * FS_H2 + 16 + q * 8 + tig + 4];
                const uint2* br = s_wl2p + (q * 4 + tig) * WH32 + gid;
                #pragma unroll
                for (int n = 0; n < 4; n++) {
                    uint2 bb = br[8 * n];
                    mma_f16(ac0[n], a00, a01, a02, a03, bb.x, bb.y);
                    mma_f16(ac1[n], a10, a11, a12, a13, bb.x, bb.y);
                }
            }
            #pragma unroll
            for (int n = 0; n < 4; n++) {
                int c0 = n * 8 + 2 * tig;
                float b0 = s_vec[32 + c0], b1 = s_vec[32 + c0 + 1];
                g_fx2[((size_t)p0 * KNN + gid) * 16 + (c0 >> 1)] =
                    __floats2half2_rn(fmaxf(ac0[n][0] + b0, 0.f), fmaxf(ac0[n][1] + b1, 0.f));
                g_fx2[((size_t)p0 * KNN + gid + 8) * 16 + (c0 >> 1)] =
                    __floats2half2_rn(fmaxf(ac0[n][2] + b0, 0.f), fmaxf(ac0[n][3] + b1, 0.f));
                g_fx2[((size_t)p1 * KNN + gid) * 16 + (c0 >> 1)] =
                    __floats2half2_rn(fmaxf(ac1[n][0] + b0, 0.f), fmaxf(ac1[n][1] + b1, 0.f));
                g_fx2[((size_t)p1 * KNN + gid + 8) * 16 + (c0 >> 1)] =
                    __floats2half2_rn(fmaxf(ac1[n][2] + b0, 0.f), fmaxf(ac1[n][3] + b1, 0.f));
            }
        }
        __syncwarp();
    }
}

// ---------------------------------------------------------------------------
// Kernel 3: TWO points per warp: idx-prefetch (1 reg); fp16 gather + fx2 +
//           logits->exp + pools -> g_agg2.  23 warps.
// ---------------------------------------------------------------------------
#define K3_WARP_FLOATS 2304
#define K3_BASE_FLOATS 2176
#define K3_WARPS 23
#define K3_SMEM_BYTES ((K3_BASE_FLOATS + K3_WARPS * K3_WARP_FLOATS) * 4)

__global__ __launch_bounds__(736) void kern_att2(
    const int* __restrict__ neigh,
    const float* __restrict__ wfc2)
{
    extern __shared__ float sm[];
    uint2* s_wfcp = (uint2*)sm;               // [16][68] uint2
    float* s_wrp  = sm + K3_BASE_FLOATS;

    for (int i = threadIdx.x; i < 1024; i += blockDim.x) {
        int r = i >> 6, c = i & 63;
        int q = r >> 2, t = r & 3;
        int k0 = 16 * q + 2 * t;
        s_wfcp[r * WH64 + c] = make_uint2(
            f2_to_u(wfc2[k0 * 64 + c], wfc2[(k0 + 1) * 64 + c]),
            f2_to_u(wfc2[(k0 + 8) * 64 + c], wfc2[(k0 + 9) * 64 + c]));
    }
    __syncthreads();

    const int lane = threadIdx.x & 31;
    const int warp = threadIdx.x >> 5;
    float* wbase = s_wrp + warp * K3_WARP_FLOATS;
    __half2*  fs0_h = (__half2*)wbase;
    __half2*  fs1_h = (__half2*)(wbase + 576);
    unsigned* fsw0  = (unsigned*)fs0_h;
    unsigned* fsw1  = (unsigned*)fs1_h;
    __half2*  elg0  = (__half2*)(wbase + 1152);
    __half2*  elg1  = (__half2*)(wbase + 1728);

    const int kk = lane >> 4;
    const int jj = lane & 15;

    const unsigned* fah = (const unsigned*)g_f_agg_h;

    const int nwarps = (gridDim.x * blockDim.x) >> 5;
    int gw = (blockIdx.x * blockDim.x + threadIdx.x) >> 5;

    // prefetch first iteration's neighbor row (1 register)
    int idx = (gw < PHALF) ? neigh[(size_t)(2 * gw) * KNN + lane] : 0;

    for (int pp = gw; pp < PHALF; pp += nwarps) {
        const int p0 = 2 * pp, p1 = p0 + 1;
        const int b = p0 / NPTS;
        const size_t bbase = (size_t)b * NPTS;

        #pragma unroll
        for (int k = 0; k < KNN; k += 2) {
            int nb = __shfl_sync(0xffffffffu, idx, k + kk);
            fsw0[(k + kk) * FS_H2 + jj] = fah[(bbase + (size_t)nb) * 16 + jj];
        }
        #pragma unroll
        for (int k = 0; k < KNN; k += 2) {
            int nb = __shfl_sync(0xffffffffu, idx, 16 + k + kk);
            fsw1[(k + kk) * FS_H2 + jj] = fah[(bbase + (size_t)nb) * 16 + jj];
        }
        const unsigned* src0 = (const unsigned*)(g_fx2 + (size_t)p0 * KNN * 16);
        const unsigned* src1 = (const unsigned*)(g_fx2 + (size_t)p1 * KNN * 16);
        #pragma unroll
        for (int k = 0; k < KNN; k += 2) {
            fsw0[(k + kk) * FS_H2 + 16 + jj] = src0[(k + kk) * 16 + jj];
            fsw1[(k + kk) * FS_H2 + 16 + jj] = src1[(k + kk) * 16 + jj];
        }

        // idx dead -- prefetch next iteration's neighbor row
        {
            int ppn = pp + nwarps;
            if (ppn < PHALF) idx = neigh[(size_t)(2 * ppn) * KNN + lane];
        }
        __syncwarp();

        logits_exp_x2(fsw0, fsw1, elg0, elg1, s_wfcp, lane);
        __syncwarp();

        *(float2*)(&g_agg2[(size_t)p0 * 64 + 2 * lane]) = att_pool_e2(elg0, fs0_h, lane);
        *(float2*)(&g_agg2[(size_t)p1 * 64 + 2 * lane]) = att_pool_e2(elg1, fs1_h, lane);
        __syncwarp();
    }
}

// ---------------------------------------------------------------------------
// Kernel 4: 16-point tiles, SINGLE TF32 GEMMs with float2-packed B. 18 warps.
// (Round-15 version: GEMM2 in two n-halves)
// ---------------------------------------------------------------------------
#define OUT_WARPS 18
#define OUT_BASE_FLOATS 17216
#define OUT_WARP_FLOATS 1600
#define OUT_SMEM_BYTES ((OUT_BASE_FLOATS + OUT_WARPS * OUT_WARP_FLOATS) * 4)

__global__ __launch_bounds__(576) void kern_out(
    const float* __restrict__ feature,
    const float* __restrict__ wam2, const float* __restrict__ sam2, const float* __restrict__ bam2,
    const float* __restrict__ wmlp2, const float* __restrict__ smlp2, const float* __restrict__ bmlp2,
    const float* __restrict__ wsc, const float* __restrict__ ssc, const float* __restrict__ bsc,
    float* __restrict__ out)
{
    extern __shared__ float sm[];
    float2* w1p  = (float2*)sm;              // [32][68] float2 = 4352 floats
    float2* w23p = (float2*)(sm + 4352);     // [48][132] float2 = 12672 floats
    float*  b1   = sm + 17024;               // [64]
    float*  b2   = sm + 17088;               // [128]
    float*  wrp  = sm + OUT_BASE_FLOATS;

    for (int i = threadIdx.x; i < 2048; i += blockDim.x) {
        int r = i >> 6, c = i & 63;
        int k0 = (r >> 2) * 8 + (r & 3), k1 = k0 + 4;
        w1p[r * P2F64 + c] = make_float2(to_tf32(wam2[k0 * 64 + c] * sam2[c]),
                                         to_tf32(wam2[k1 * 64 + c] * sam2[c]));
    }
    for (int i = threadIdx.x; i < 6144; i += blockDim.x) {
        int r = i >> 7, c = i & 127;
        int k0 = (r >> 2) * 8 + (r & 3), k1 = k0 + 4;
        float v0 = (k0 < 64) ? wmlp2[k0 * 128 + c] * smlp2[c] : wsc[(k0 - 64) * 128 + c] * ssc[c];
        float v1 = (k1 < 64) ? wmlp2[k1 * 128 + c] * smlp2[c] : wsc[(k1 - 64) * 128 + c] * ssc[c];
        w23p[r * P2F128 + c] = make_float2(to_tf32(v0), to_tf32(v1));
    }
    if (threadIdx.x < 64)  b1[threadIdx.x] = bam2[threadIdx.x];
    if (threadIdx.x < 128) b2[threadIdx.x] = bmlp2[threadIdx.x] + bsc[threadIdx.x];
    __syncthreads();

    const int lane = threadIdx.x & 31;
    const int warp = threadIdx.x >> 5;
    const int gid = lane >> 2, tig = lane & 3;
    float* A1 = wrp + warp * OUT_WARP_FLOATS;  // [16][100]

    const int nwarps = (gridDim.x * blockDim.x) >> 5;
    int gw = (blockIdx.x * blockDim.x + threadIdx.x) >> 5;
    const int ntiles = P_TOTAL / 16;

    for (int t = gw; t < ntiles; t += nwarps) {
        const int p0 = t * 16;

        #pragma unroll
        for (int r = 0; r < 16; r++) {
            A1[r * OA_PAD + lane]      = g_agg2[(size_t)(p0 + r) * 64 + lane];
            A1[r * OA_PAD + 32 + lane] = g_agg2[(size_t)(p0 + r) * 64 + 32 + lane];
            A1[r * OA_PAD + 64 + lane] = feature[(size_t)(p0 + r) * 32 + lane];
        }
        __syncwarp();

        // GEMM1 (single tf32): pc2 = relu(agg @ w1 + b1) -> A cols 0..63
        {
            float acc[8][4];
            #pragma unroll
            for (int n = 0; n < 8; n++) { acc[n][0]=0.f; acc[n][1]=0.f; acc[n][2]=0.f; acc[n][3]=0.f; }
            #pragma unroll
            for (int q = 0; q < 8; q++) {
                unsigned a0 = __float_as_uint(to_tf32(A1[gid * OA_PAD + q * 8 + tig]));
                unsigned a1 = __float_as_uint(to_tf32(A1[(gid + 8) * OA_PAD + q * 8 + tig]));
                unsigned a2 = __float_as_uint(to_tf32(A1[gid * OA_PAD + q * 8 + tig + 4]));
                unsigned a3 = __float_as_uint(to_tf32(A1[(gid + 8) * OA_PAD + q * 8 + tig + 4]));
                const float2* br = w1p + (q * 4 + tig) * P2F64 + gid;
                #pragma unroll
                for (int n = 0; n < 8; n++) {
                    float2 b = br[8 * n];
                    mma_tf32(acc[n], a0, a1, a2, a3,
                             __float_as_uint(b.x), __float_as_uint(b.y));
                }
            }
            __syncwarp();
            #pragma unroll
            for (int n = 0; n < 8; n++) {
                int c0 = n * 8 + 2 * tig;
                float bb0 = b1[c0], bb1 = b1[c0 + 1];
                *(float2*)(A1 + gid * OA_PAD + c0) =
                    make_float2(fmaxf(acc[n][0] + bb0, 0.f), fmaxf(acc[n][1] + bb1, 0.f));
                *(float2*)(A1 + (gid + 8) * OA_PAD + c0) =
                    make_float2(fmaxf(acc[n][2] + bb0, 0.f), fmaxf(acc[n][3] + bb1, 0.f));
            }
        }
        __syncwarp();

        // GEMM2 (single tf32): out = leaky(A[16][96] @ w23 + b2), two n-halves
        #pragma unroll
        for (int h = 0; h < 2; h++) {
            float acc[8][4];
            #pragma unroll
            for (int n = 0; n < 8; n++) { acc[n][0]=0.f; acc[n][1]=0.f; acc[n][2]=0.f; acc[n][3]=0.f; }
            #pragma unroll
            for (int q = 0; q < 12; q++) {
                unsigned a0 = __float_as_uint(to_tf32(A1[gid * OA_PAD + q * 8 + tig]));
                unsigned a1 = __float_as_uint(to_tf32(A1[(gid + 8) * OA_PAD + q * 8 + tig]));
                unsigned a2 = __float_as_uint(to_tf32(A1[gid * OA_PAD + q * 8 + tig + 4]));
                unsigned a3 = __float_as_uint(to_tf32(A1[(gid + 8) * OA_PAD + q * 8 + tig + 4]));
                const float2* br = w23p + (q * 4 + tig) * P2F128 + h * 64 + gid;
                #pragma unroll
                for (int n = 0; n < 8; n++) {
                    float2 b = br[8 * n];
                    mma_tf32(acc[n], a0, a1, a2, a3,
                             __float_as_uint(b.x), __float_as_uint(b.y));
                }
            }
            #pragma unroll
            for (int n = 0; n < 8; n++) {
                int c0 = h * 64 + n * 8 + 2 * tig;
                float bb0 = b2[c0], bb1 = b2[c0 + 1];
                float v0 = acc[n][0] + bb0; v0 = (v0 < 0.f) ? 0.2f * v0 : v0;
                float v1 = acc[n][1] + bb1; v1 = (v1 < 0.f) ? 0.2f * v1 : v1;
                float v2 = acc[n][2] + bb0; v2 = (v2 < 0.f) ? 0.2f * v2 : v2;
                float v3 = acc[n][3] + bb1; v3 = (v3 < 0.f) ? 0.2f * v3 : v3;
                *(float2*)(&out[(size_t)(p0 + gid) * 128 + c0])     = make_float2(v0, v1);
                *(float2*)(&out[(size_t)(p0 + gid + 8) * 128 + c0]) = make_float2(v2, v3);
            }
        }
        __syncwarp();
    }
}

// ---------------------------------------------------------------------------
extern "C" void kernel_launch(void* const* d_in, const int* in_sizes, int n_in,
                              void* d_out, int out_size)
{
    const float* feature = (const float*)d_in[0];
    const float* xyz     = (const float*)d_in[1];
    const int*   neigh   = (const int*)  d_in[2];
    const float* w_mlp1  = (const float*)d_in[3];
    const float* s_mlp1  = (const float*)d_in[4];
    const float* b_mlp1  = (const float*)d_in[5];
    const float* w_lfa1  = (const float*)d_in[6];
    const float* s_lfa1  = (const float*)d_in[7];
    const float* b_lfa1  = (const float*)d_in[8];
    const float* w_fc1   = (const float*)d_in[9];
    const float* w_am1   = (const float*)d_in[10];
    const float* s_am1   = (const float*)d_in[11];
    const float* b_am1   = (const float*)d_in[12];
    const float* w_lfa2  = (const float*)d_in[13];
    const float* s_lfa2  = (const float*)d_in[14];
    const float* b_lfa2  = (const float*)d_in[15];
    const float* w_fc2   = (const float*)d_in[16];
    const float* w_am2   = (const float*)d_in[17];
    const float* s_am2   = (const float*)d_in[18];
    const float* b_am2   = (const float*)d_in[19];
    const float* w_mlp2  = (const float*)d_in[20];
    const float* s_mlp2  = (const float*)d_in[21];
    const float* b_mlp2  = (const float*)d_in[22];
    const float* w_sc    = (const float*)d_in[23];
    const float* s_sc    = (const float*)d_in[24];
    const float* b_sc    = (const float*)d_in[25];
    float* out = (float*)d_out;

    cudaFuncSetAttribute(kern_att1, cudaFuncAttributeMaxDynamicSharedMemorySize, K2_SMEM_BYTES);
    cudaFuncSetAttribute(kern_att2, cudaFuncAttributeMaxDynamicSharedMemorySize, K3_SMEM_BYTES);
    cudaFuncSetAttribute(kern_out,  cudaFuncAttributeMaxDynamicSharedMemorySize, OUT_SMEM_BYTES);

    kern_mlp1<<<2048, 256>>>(feature, w_mlp1, s_mlp1, b_mlp1);

    kern_att1<<<148, 640, K2_SMEM_BYTES>>>(
        xyz, neigh,
        w_lfa1, s_lfa1, b_lfa1,
        w_fc1,
        w_am1, s_am1, b_am1,
        w_lfa2, s_lfa2, b_lfa2);

    kern_att2<<<148, 736, K3_SMEM_BYTES>>>(neigh, w_fc2);

    kern_out<<<148, 576, OUT_SMEM_BYTES>>>(
        feature,
        w_am2, s_am2, b_am2,
        w_mlp2, s_mlp2, b_mlp2,
        w_sc, s_sc, b_sc,
        out);
}